// round 1
// baseline (speedup 1.0000x reference)
#include <cuda_runtime.h>
#include <math.h>

#define N_NODES 50000
#define N_EDGES 600000
// D = 128, HIDDEN = 128

// Scratch: UV[node][0:128] = z[node] @ W1[0:128,:], UV[node][128:256] = z[node] @ W1[128:256,:]
__device__ float g_UV[(size_t)N_NODES * 256];

// ---------------------------------------------------------------------------
// Kernel 1: UV = z @ Wcat   (M=50000, K=128, N=256)
// Wcat[k][j] = (j < 128) ? W1[k][j] : W1[128+k][j-128]
// Tiling: BM=64, BN=64 (grid.y selects one of 4 N-blocks), BK=64 (2 k-tiles)
// 256 threads, each computes a 4x4 register tile.
// ---------------------------------------------------------------------------
__global__ __launch_bounds__(256) void uv_gemm_kernel(
    const float* __restrict__ z, const float* __restrict__ W1)
{
    __shared__ float As[64][68];   // [m][k], padded (68*4B = 272B, 16B aligned)
    __shared__ float Bs[64][64];   // [k][n]

    const int m0 = blockIdx.x * 64;
    const int bn = blockIdx.y;             // 0..3
    const int tid = threadIdx.x;
    const int tx = tid & 15, ty = tid >> 4;
    const int row0 = ty * 4, col0 = tx * 4;
    const bool hi = (bn >= 2);             // second half of concat -> W1 rows 128..255
    const int jbase = bn * 64 - (hi ? 128 : 0);  // column offset within W1 row

    float acc[4][4] = {};

    #pragma unroll
    for (int kt = 0; kt < 2; kt++) {
        // --- load A tile: 64 rows x 64 k, float4, coalesced ---
        #pragma unroll
        for (int i = tid; i < 64 * 16; i += 256) {
            int m = i >> 4, k4 = i & 15;
            int gm = m0 + m;
            float4 v = make_float4(0.f, 0.f, 0.f, 0.f);
            if (gm < N_NODES)
                v = *(const float4*)(z + (size_t)gm * 128 + kt * 64 + k4 * 4);
            *(float4*)(&As[m][k4 * 4]) = v;
        }
        // --- load B tile: 64 k x 64 n ---
        #pragma unroll
        for (int i = tid; i < 64 * 16; i += 256) {
            int k = i >> 4, j4 = i & 15;
            int wrow = (hi ? 128 : 0) + kt * 64 + k;
            float4 v = *(const float4*)(W1 + (size_t)wrow * 128 + jbase + j4 * 4);
            *(float4*)(&Bs[k][j4 * 4]) = v;
        }
        __syncthreads();

        #pragma unroll 8
        for (int k = 0; k < 64; k++) {
            float4 bv = *(float4*)(&Bs[k][col0]);
            #pragma unroll
            for (int i = 0; i < 4; i++) {
                float a = As[row0 + i][k];   // 2-way broadcast within warp
                acc[i][0] += a * bv.x;
                acc[i][1] += a * bv.y;
                acc[i][2] += a * bv.z;
                acc[i][3] += a * bv.w;
            }
        }
        __syncthreads();
    }

    // --- store 4x4 tile to g_UV ---
    #pragma unroll
    for (int i = 0; i < 4; i++) {
        int gm = m0 + row0 + i;
        if (gm < N_NODES) {
            float4 v = make_float4(acc[i][0], acc[i][1], acc[i][2], acc[i][3]);
            *(float4*)(g_UV + (size_t)gm * 256 + bn * 64 + col0) = v;
        }
    }
}

// ---------------------------------------------------------------------------
// Kernel 2: per-edge epilogue. One warp per edge.
//   h = relu(U[e0] + V[e1] + b1);  out = sigmoid(h . W2 + b2)
// Each lane handles 4 of the 128 hidden units (one float4 from U and V).
// ---------------------------------------------------------------------------
__global__ __launch_bounds__(256) void edge_kernel(
    const int* __restrict__ e32,
    const float* __restrict__ b1, const float* __restrict__ W2,
    const float* __restrict__ b2, float* __restrict__ out)
{
    __shared__ float b1s[128], w2s[128];
    __shared__ int is64s;

    const int tid = threadIdx.x;
    if (tid < 128) { b1s[tid] = b1[tid]; w2s[tid] = W2[tid]; }
    if (tid == 0) {
        // int64 little-endian index data has zero high words.
        int any_hi = 0;
        #pragma unroll
        for (int i = 1; i < 64; i += 2) any_hi |= e32[i];
        is64s = (any_hi == 0);
    }
    __syncthreads();

    const int warp = tid >> 5, lane = tid & 31;
    const int eidx = blockIdx.x * 8 + warp;      // 8 warps/block, grid sized exactly
    if (eidx >= N_EDGES) return;

    int s, t;
    if (is64s) {
        const long long* e64 = (const long long*)e32;
        s = (int)e64[eidx];
        t = (int)e64[(size_t)N_EDGES + eidx];
    } else {
        s = e32[eidx];
        t = e32[(size_t)N_EDGES + eidx];
    }

    float4 u = *(const float4*)(g_UV + (size_t)s * 256 + lane * 4);
    float4 v = *(const float4*)(g_UV + (size_t)t * 256 + 128 + lane * 4);
    float4 bb = *(const float4*)(b1s + lane * 4);
    float4 ww = *(const float4*)(w2s + lane * 4);

    float h0 = fmaxf(u.x + v.x + bb.x, 0.f);
    float h1 = fmaxf(u.y + v.y + bb.y, 0.f);
    float h2 = fmaxf(u.z + v.z + bb.z, 0.f);
    float h3 = fmaxf(u.w + v.w + bb.w, 0.f);

    float acc = h0 * ww.x + h1 * ww.y + h2 * ww.z + h3 * ww.w;
    #pragma unroll
    for (int o = 16; o > 0; o >>= 1)
        acc += __shfl_xor_sync(0xFFFFFFFFu, acc, o);

    if (lane == 0) {
        float logit = acc + b2[0];
        out[eidx] = 1.0f / (1.0f + expf(-logit));
    }
}

// ---------------------------------------------------------------------------
// Launch
// ---------------------------------------------------------------------------
extern "C" void kernel_launch(void* const* d_in, const int* in_sizes, int n_in,
                              void* d_out, int out_size)
{
    const float* z  = (const float*)d_in[0];
    const int*   e  = (const int*)d_in[1];   // dtype resolved at runtime
    const float* W1 = (const float*)d_in[2];
    const float* b1 = (const float*)d_in[3];
    const float* W2 = (const float*)d_in[4];
    const float* b2 = (const float*)d_in[5];
    float* out = (float*)d_out;

    dim3 g1((N_NODES + 63) / 64, 4);
    uv_gemm_kernel<<<g1, 256>>>(z, W1);

    edge_kernel<<<N_EDGES / 8, 256>>>(e, b1, W2, b2, out);
}

// round 6
// speedup vs baseline: 1.2538x; 1.2538x over previous
#include <cuda_runtime.h>
#include <cuda_fp16.h>
#include <math.h>

#define N_NODES 50000
#define N_EDGES 600000

// Scratch: UVh[node][0:128] = z[node]@W1[0:128,:] + b1   (bias folded into U)
//          UVh[node][128:256] = z[node]@W1[128:256,:]
__device__ __half g_UVh[(size_t)N_NODES * 256];

// ---------------------------------------------------------------------------
// Kernel 1: UV = z @ Wcat  (M=50000, K=128, N=256), fp32 compute via FFMA2,
// fp16 output with b1 folded into the U half.
// BM=64, BN=64 (grid.y = 4 N-blocks), BK=64, 256 threads, 4x4 per thread.
// ---------------------------------------------------------------------------
__global__ __launch_bounds__(256) void uv_gemm_kernel(
    const float* __restrict__ z, const float* __restrict__ W1,
    const float* __restrict__ b1)
{
    __shared__ float As[64][68];   // [m][k], padded
    __shared__ float Bs[64][64];   // [k][n]

    const int m0 = blockIdx.x * 64;
    const int bn = blockIdx.y;             // 0..3
    const int tid = threadIdx.x;
    const int tx = tid & 15, ty = tid >> 4;
    const int row0 = ty * 4, col0 = tx * 4;
    const bool hi = (bn >= 2);             // V half -> W1 rows 128..255
    const int jbase = bn * 64 - (hi ? 128 : 0);

    // packed accumulators: [row][colpair], each holds 2 fp32 lanes
    unsigned long long acc2[4][2];
    #pragma unroll
    for (int i = 0; i < 4; i++) { acc2[i][0] = 0ull; acc2[i][1] = 0ull; }

    #pragma unroll
    for (int kt = 0; kt < 2; kt++) {
        #pragma unroll
        for (int i = tid; i < 64 * 16; i += 256) {
            int m = i >> 4, k4 = i & 15;
            int gm = m0 + m;
            float4 v = make_float4(0.f, 0.f, 0.f, 0.f);
            if (gm < N_NODES)
                v = *(const float4*)(z + (size_t)gm * 128 + kt * 64 + k4 * 4);
            *(float4*)(&As[m][k4 * 4]) = v;
        }
        #pragma unroll
        for (int i = tid; i < 64 * 16; i += 256) {
            int k = i >> 4, j4 = i & 15;
            int wrow = (hi ? 128 : 0) + kt * 64 + k;
            float4 v = *(const float4*)(W1 + (size_t)wrow * 128 + jbase + j4 * 4);
            *(float4*)(&Bs[k][j4 * 4]) = v;
        }
        __syncthreads();

        #pragma unroll 8
        for (int k = 0; k < 64; k++) {
            // two natural 64-bit column pairs from one 16B shared load
            const ulonglong2 bp = *(const ulonglong2*)(&Bs[k][col0]);
            #pragma unroll
            for (int i = 0; i < 4; i++) {
                unsigned int a = __float_as_uint(As[row0 + i][k]);
                unsigned long long ad;
                asm("mov.b64 %0, {%1, %1};" : "=l"(ad) : "r"(a));
                asm("fma.rn.f32x2 %0, %1, %2, %0;" : "+l"(acc2[i][0]) : "l"(ad), "l"(bp.x));
                asm("fma.rn.f32x2 %0, %1, %2, %0;" : "+l"(acc2[i][1]) : "l"(ad), "l"(bp.y));
            }
        }
        __syncthreads();
    }

    // epilogue: unpack, fold b1 into U half, convert to fp16, store 8B
    float4 b1v = make_float4(0.f, 0.f, 0.f, 0.f);
    if (!hi) b1v = *(const float4*)(b1 + bn * 64 + col0);

    #pragma unroll
    for (int i = 0; i < 4; i++) {
        int gm = m0 + row0 + i;
        if (gm < N_NODES) {
            float2 c01 = *(float2*)(&acc2[i][0]);
            float2 c23 = *(float2*)(&acc2[i][1]);
            __half2 h01 = __floats2half2_rn(c01.x + b1v.x, c01.y + b1v.y);
            __half2 h23 = __floats2half2_rn(c23.x + b1v.z, c23.y + b1v.w);
            __half2* dst = (__half2*)(g_UVh + (size_t)gm * 256 + bn * 64 + col0);
            dst[0] = h01;
            dst[1] = h23;
        }
    }
}

// ---------------------------------------------------------------------------
// Kernel 2: per-edge epilogue, one warp per edge, persistent grid-stride loop.
//   h = relu(U'[e0] + V[e1]);  out = sigmoid(h . W2 + b2)
// W2 lives in registers (loaded once per warp); no shared-memory loads in loop.
// Each lane handles 4 hidden units: 8B fp16 loads from U and V.
// ---------------------------------------------------------------------------
__global__ __launch_bounds__(256) void edge_kernel(
    const int* __restrict__ e32,
    const float* __restrict__ W2, const float* __restrict__ b2,
    float* __restrict__ out)
{
    __shared__ int is64s;
    const int tid = threadIdx.x;
    if (tid == 0) {
        int any_hi = 0;
        #pragma unroll
        for (int i = 1; i < 64; i += 2) any_hi |= e32[i];
        is64s = (any_hi == 0);
    }
    __syncthreads();
    const int is64 = is64s;

    const int warp = tid >> 5, lane = tid & 31;
    const float4 ww = *(const float4*)(W2 + lane * 4);
    const float bias2 = __ldg(b2);

    const int nwarps = gridDim.x * 8;
    const long long* e64 = (const long long*)e32;

    for (int e = blockIdx.x * 8 + warp; e < N_EDGES; e += nwarps) {
        int s, t;
        if (is64) {
            s = (int)e64[e];
            t = (int)e64[(size_t)N_EDGES + e];
        } else {
            s = e32[e];
            t = e32[(size_t)N_EDGES + e];
        }

        uint2 ud = *(const uint2*)(g_UVh + (size_t)s * 256 + lane * 4);
        uint2 vd = *(const uint2*)(g_UVh + (size_t)t * 256 + 128 + lane * 4);

        float2 u01 = __half22float2(*(__half2*)&ud.x);
        float2 u23 = __half22float2(*(__half2*)&ud.y);
        float2 v01 = __half22float2(*(__half2*)&vd.x);
        float2 v23 = __half22float2(*(__half2*)&vd.y);

        float h0 = fmaxf(u01.x + v01.x, 0.f);
        float h1 = fmaxf(u01.y + v01.y, 0.f);
        float h2 = fmaxf(u23.x + v23.x, 0.f);
        float h3 = fmaxf(u23.y + v23.y, 0.f);

        float acc = h0 * ww.x + h1 * ww.y + h2 * ww.z + h3 * ww.w;
        #pragma unroll
        for (int o = 16; o > 0; o >>= 1)
            acc += __shfl_xor_sync(0xFFFFFFFFu, acc, o);

        if (lane == 0) {
            float logit = acc + bias2;
            out[e] = 1.0f / (1.0f + expf(-logit));
        }
    }
}

// ---------------------------------------------------------------------------
extern "C" void kernel_launch(void* const* d_in, const int* in_sizes, int n_in,
                              void* d_out, int out_size)
{
    const float* z  = (const float*)d_in[0];
    const int*   e  = (const int*)d_in[1];
    const float* W1 = (const float*)d_in[2];
    const float* b1 = (const float*)d_in[3];
    const float* W2 = (const float*)d_in[4];
    const float* b2 = (const float*)d_in[5];
    float* out = (float*)d_out;

    dim3 g1((N_NODES + 63) / 64, 4);
    uv_gemm_kernel<<<g1, 256>>>(z, W1, b1);

    edge_kernel<<<1184, 256>>>(e, W2, b2, out);
}

// round 8
// speedup vs baseline: 1.7288x; 1.3789x over previous
#include <cuda_runtime.h>
#include <cuda_fp16.h>
#include <math.h>

#define N_NODES 50000
#define N_EDGES 600000

// UVh[node][0:128] = z@W1[0:128,:] + b1 ; UVh[node][128:256] = z@W1[128:256,:]
__device__ __half g_UVh[(size_t)N_NODES * 256];

__device__ __forceinline__ unsigned smem_u32(const void* p) {
    return (unsigned)__cvta_generic_to_shared(p);
}

// ---------------------------------------------------------------------------
// Kernel 1: tensor-core GEMM. UV = z @ Wcat (M=50000, K=128, N=256), fp16 in,
// f32 accum, fp16 out with b1 folded into the U half.
// One block = 64 M-rows; loops over all 4 N-tiles of 64 (z loaded ONCE).
// 256 threads = 8 warps in 2(m) x 4(n); warp tile 32m x 16n via m16n8k16.
// ---------------------------------------------------------------------------
__global__ __launch_bounds__(256) void uv_gemm_tc(
    const float* __restrict__ z, const float* __restrict__ W1,
    const float* __restrict__ b1)
{
    __shared__ __half Ah[64][136];   // [m][k], pad 8 halves -> conflict-free ldmatrix
    __shared__ __half Bh[64][136];   // [n][k] (W1 transposed tile)

    const int tid = threadIdx.x;
    const int m0 = blockIdx.x * 64;
    const int wid = tid >> 5, lane = tid & 31;
    const int warp_m = wid >> 2;     // 0..1
    const int warp_n = wid & 3;      // 0..3
    const int l15 = lane & 15;

    // --- A tile: 64 rows x 128 k, fp32 -> fp16 ---
    #pragma unroll
    for (int i = tid; i < 64 * 32; i += 256) {
        int r = i >> 5, c4 = i & 31;
        float4 v = make_float4(0.f, 0.f, 0.f, 0.f);
        int gm = m0 + r;
        if (gm < N_NODES) v = *(const float4*)(z + (size_t)gm * 128 + c4 * 4);
        __half2* dst = (__half2*)&Ah[r][c4 * 4];
        dst[0] = __floats2half2_rn(v.x, v.y);
        dst[1] = __floats2half2_rn(v.z, v.w);
    }

    #pragma unroll
    for (int bn = 0; bn < 4; bn++) {
        const bool hi = (bn >= 2);               // V half -> W1 rows 128..255
        const int jbase = bn * 64 - (hi ? 128 : 0);
        const int wbase = hi ? 128 : 0;

        __syncthreads();   // Ah ready (bn=0) / prior Bh consumers done (bn>0)

        // --- B tile: Bh[n][k] = W1[wbase+k][jbase+n], coalesced in n ---
        {
            int n = tid & 63;
            int k0 = tid >> 6;                   // 0..3
            #pragma unroll
            for (int k = k0; k < 128; k += 4)
                Bh[n][k] = __float2half_rn(W1[(size_t)(wbase + k) * 128 + jbase + n]);
        }
        __syncthreads();

        float acc[2][2][4];
        #pragma unroll
        for (int tm = 0; tm < 2; tm++)
            #pragma unroll
            for (int tn = 0; tn < 2; tn++)
                #pragma unroll
                for (int i = 0; i < 4; i++) acc[tm][tn][i] = 0.f;

        #pragma unroll
        for (int kb = 0; kb < 8; kb++) {
            unsigned a[2][4], b[2][2];
            #pragma unroll
            for (int tm = 0; tm < 2; tm++) {
                int row = warp_m * 32 + tm * 16 + l15;
                int col = kb * 16 + (lane >> 4) * 8;
                unsigned addr = smem_u32(&Ah[row][col]);
                asm volatile("ldmatrix.sync.aligned.m8n8.x4.shared.b16 {%0,%1,%2,%3}, [%4];"
                    : "=r"(a[tm][0]), "=r"(a[tm][1]), "=r"(a[tm][2]), "=r"(a[tm][3])
                    : "r"(addr));
            }
            #pragma unroll
            for (int tn = 0; tn < 2; tn++) {
                int rown = warp_n * 16 + tn * 8 + (l15 & 7);
                int col = kb * 16 + (l15 >> 3) * 8;
                unsigned addr = smem_u32(&Bh[rown][col]);
                asm volatile("ldmatrix.sync.aligned.m8n8.x2.shared.b16 {%0,%1}, [%2];"
                    : "=r"(b[tn][0]), "=r"(b[tn][1]) : "r"(addr));
            }
            #pragma unroll
            for (int tm = 0; tm < 2; tm++)
                #pragma unroll
                for (int tn = 0; tn < 2; tn++)
                    asm volatile("mma.sync.aligned.m16n8k16.row.col.f32.f16.f16.f32 "
                        "{%0,%1,%2,%3},{%4,%5,%6,%7},{%8,%9},{%0,%1,%2,%3};"
                        : "+f"(acc[tm][tn][0]), "+f"(acc[tm][tn][1]),
                          "+f"(acc[tm][tn][2]), "+f"(acc[tm][tn][3])
                        : "r"(a[tm][0]), "r"(a[tm][1]), "r"(a[tm][2]), "r"(a[tm][3]),
                          "r"(b[tn][0]), "r"(b[tn][1]));
        }

        // --- epilogue: fold b1 into U half, fp16 store ---
        #pragma unroll
        for (int tm = 0; tm < 2; tm++) {
            #pragma unroll
            for (int tn = 0; tn < 2; tn++) {
                int c = warp_n * 16 + tn * 8 + 2 * (lane & 3);   // within 64-col tile
                float bx = 0.f, by = 0.f;
                if (!hi) {
                    bx = b1[bn * 64 + c];
                    by = b1[bn * 64 + c + 1];
                }
                int r0 = m0 + warp_m * 32 + tm * 16 + (lane >> 2);
                int r1 = r0 + 8;
                if (r0 < N_NODES)
                    *(__half2*)(g_UVh + (size_t)r0 * 256 + bn * 64 + c) =
                        __floats2half2_rn(acc[tm][tn][0] + bx, acc[tm][tn][1] + by);
                if (r1 < N_NODES)
                    *(__half2*)(g_UVh + (size_t)r1 * 256 + bn * 64 + c) =
                        __floats2half2_rn(acc[tm][tn][2] + bx, acc[tm][tn][3] + by);
            }
        }
    }
}

// ---------------------------------------------------------------------------
// Kernel 2: edge epilogue. 16 lanes per edge, 2 edges per warp, half2 math.
//   h = relu(U'[e0] + V[e1]);  out = sigmoid(h . W2 + b2)
// Lane loads 16B from U and 16B from V (8 hidden units each).
// ---------------------------------------------------------------------------
__global__ __launch_bounds__(256) void edge_kernel(
    const int* __restrict__ e32,
    const float* __restrict__ W2, const float* __restrict__ b2,
    float* __restrict__ out)
{
    __shared__ int is64s;
    const int tid = threadIdx.x;
    if (tid == 0) {
        int any_hi = 0;
        #pragma unroll
        for (int i = 1; i < 64; i += 2) any_hi |= e32[i];
        is64s = (any_hi == 0);
    }
    __syncthreads();
    const int is64 = is64s;

    const int warp = tid >> 5, lane = tid & 31;
    const int g  = lane >> 4;        // which edge of the pair
    const int sl = lane & 15;        // lane within edge group

    // W2 slice for this lane: 8 fp32 -> 4 half2 registers
    __half2 w2h[4];
    {
        float4 wa = *(const float4*)(W2 + sl * 8);
        float4 wb = *(const float4*)(W2 + sl * 8 + 4);
        w2h[0] = __floats2half2_rn(wa.x, wa.y);
        w2h[1] = __floats2half2_rn(wa.z, wa.w);
        w2h[2] = __floats2half2_rn(wb.x, wb.y);
        w2h[3] = __floats2half2_rn(wb.z, wb.w);
    }
    const float bias2 = __ldg(b2);
    const long long* e64 = (const long long*)e32;

    const int gw = blockIdx.x * 8 + warp;
    const int stride = gridDim.x * 8 * 2;
    const __half2 z2 = __float2half2_rn(0.f);

    for (int e = gw * 2 + g; e < N_EDGES; e += stride) {
        int s, t;
        if (is64) {
            s = (int)e64[e];
            t = (int)e64[(size_t)N_EDGES + e];
        } else {
            s = e32[e];
            t = e32[(size_t)N_EDGES + e];
        }

        uint4 ud = *(const uint4*)(g_UVh + (size_t)s * 256 + sl * 8);
        uint4 vd = *(const uint4*)(g_UVh + (size_t)t * 256 + 128 + sl * 8);

        __half2 h0 = __hmax2(__hadd2(*(__half2*)&ud.x, *(__half2*)&vd.x), z2);
        __half2 h1 = __hmax2(__hadd2(*(__half2*)&ud.y, *(__half2*)&vd.y), z2);
        __half2 h2 = __hmax2(__hadd2(*(__half2*)&ud.z, *(__half2*)&vd.z), z2);
        __half2 h3 = __hmax2(__hadd2(*(__half2*)&ud.w, *(__half2*)&vd.w), z2);

        __half2 acc2 = __hmul2(h0, w2h[0]);
        acc2 = __hfma2(h1, w2h[1], acc2);
        acc2 = __hfma2(h2, w2h[2], acc2);
        acc2 = __hfma2(h3, w2h[3], acc2);
        float2 af = __half22float2(acc2);
        float acc = af.x + af.y;

        acc += __shfl_xor_sync(0xFFFFFFFFu, acc, 8);
        acc += __shfl_xor_sync(0xFFFFFFFFu, acc, 4);
        acc += __shfl_xor_sync(0xFFFFFFFFu, acc, 2);
        acc += __shfl_xor_sync(0xFFFFFFFFu, acc, 1);

        if (sl == 0) {
            float logit = acc + bias2;
            out[e] = 1.0f / (1.0f + expf(-logit));
        }
    }
}

// ---------------------------------------------------------------------------
extern "C" void kernel_launch(void* const* d_in, const int* in_sizes, int n_in,
                              void* d_out, int out_size)
{
    const float* z  = (const float*)d_in[0];
    const int*   e  = (const int*)d_in[1];
    const float* W1 = (const float*)d_in[2];
    const float* b1 = (const float*)d_in[3];
    const float* W2 = (const float*)d_in[4];
    const float* b2 = (const float*)d_in[5];
    float* out = (float*)d_out;

    uv_gemm_tc<<<(N_NODES + 63) / 64, 256>>>(z, W1, b1);
    edge_kernel<<<1184, 256>>>(e, W2, b2, out);
}

// round 14
// speedup vs baseline: 2.9535x; 1.7084x over previous
#include <cuda_runtime.h>
#include <cuda_fp16.h>
#include <math.h>

#define N_NODES 50000
#define N_EDGES 600000

// UVh[node][0:128] = z@W1[0:128,:] + b1 ; UVh[node][128:256] = z@W1[128:256,:]
__device__ __half g_UVh[(size_t)N_NODES * 256];
// W1t[n][k] = Wcat[k][n] in fp16:  n<128 -> W1[k][n],  n>=128 -> W1[128+k][n-128]
__device__ __half g_W1t[256 * 128];

__device__ __forceinline__ unsigned smem_u32(const void* p) {
    return (unsigned)__cvta_generic_to_shared(p);
}

// ---------------------------------------------------------------------------
// Kernel 0: one-time W1 fp32 -> fp16 transpose into [n][k] layout.
// ---------------------------------------------------------------------------
__global__ __launch_bounds__(256) void w1_convert(const float* __restrict__ W1)
{
    int idx = blockIdx.x * 256 + threadIdx.x;       // 32768 total
    int n = idx >> 7, k = idx & 127;
    int r = (n < 128) ? k : (128 + k);
    int c = n & 127;
    g_W1t[idx] = __float2half_rn(W1[(size_t)r * 128 + c]);
}

// ---------------------------------------------------------------------------
// Kernel 1: tensor-core GEMM. UV = z @ Wcat (M=50000, K=128, N=256).
// One block = 64 M-rows; loops over 4 N-tiles (z converted to smem once).
// 256 threads = 8 warps in 2(m) x 4(n); warp tile 32m x 16n via m16n8k16.
// B tiles copied vectorized from the pre-transposed fp16 W1t.
// ---------------------------------------------------------------------------
__global__ __launch_bounds__(256) void uv_gemm_tc(
    const float* __restrict__ z, const float* __restrict__ b1)
{
    __shared__ __half Ah[64][136];   // [m][k], padded -> conflict-free ldmatrix
    __shared__ __half Bh[64][136];   // [n][k]

    const int tid = threadIdx.x;
    const int m0 = blockIdx.x * 64;
    const int wid = tid >> 5, lane = tid & 31;
    const int warp_m = wid >> 2;     // 0..1
    const int warp_n = wid & 3;      // 0..3
    const int l15 = lane & 15;

    // --- A tile: 64 rows x 128 k, fp32 -> fp16 ---
    #pragma unroll
    for (int i = tid; i < 64 * 32; i += 256) {
        int r = i >> 5, c4 = i & 31;
        float4 v = make_float4(0.f, 0.f, 0.f, 0.f);
        int gm = m0 + r;
        if (gm < N_NODES) v = *(const float4*)(z + (size_t)gm * 128 + c4 * 4);
        __half2* dst = (__half2*)&Ah[r][c4 * 4];
        dst[0] = __floats2half2_rn(v.x, v.y);
        dst[1] = __floats2half2_rn(v.z, v.w);
    }

    const int bn_row = tid >> 2;          // 0..63  (row of B tile this thread fills)
    const int bq = tid & 3;               // 0..3   (base uint4 slot)

    #pragma unroll
    for (int bn = 0; bn < 4; bn++) {
        __syncthreads();   // Ah ready (bn=0) / prior Bh consumers done (bn>0)

        // --- B tile: vectorized copy of 64 rows x 128 k fp16 (16 KB).
        //     Each row = 128 halves = 16 uint4; 4 threads/row copy 4 uint4 each.
        {
            const uint4* src = (const uint4*)(g_W1t + (size_t)(bn * 64 + bn_row) * 128);
            uint4* dst = (uint4*)&Bh[bn_row][0];
            dst[bq]      = src[bq];
            dst[bq + 4]  = src[bq + 4];
            dst[bq + 8]  = src[bq + 8];
            dst[bq + 12] = src[bq + 12];
        }
        __syncthreads();

        float acc[2][2][4];
        #pragma unroll
        for (int tm = 0; tm < 2; tm++)
            #pragma unroll
            for (int tn = 0; tn < 2; tn++)
                #pragma unroll
                for (int i = 0; i < 4; i++) acc[tm][tn][i] = 0.f;

        #pragma unroll
        for (int kb = 0; kb < 8; kb++) {
            unsigned a[2][4], b[2][2];
            #pragma unroll
            for (int tm = 0; tm < 2; tm++) {
                int row = warp_m * 32 + tm * 16 + l15;
                int col = kb * 16 + (lane >> 4) * 8;
                unsigned addr = smem_u32(&Ah[row][col]);
                asm volatile("ldmatrix.sync.aligned.m8n8.x4.shared.b16 {%0,%1,%2,%3}, [%4];"
                    : "=r"(a[tm][0]), "=r"(a[tm][1]), "=r"(a[tm][2]), "=r"(a[tm][3])
                    : "r"(addr));
            }
            #pragma unroll
            for (int tn = 0; tn < 2; tn++) {
                int rown = warp_n * 16 + tn * 8 + (l15 & 7);
                int col = kb * 16 + (l15 >> 3) * 8;
                unsigned addr = smem_u32(&Bh[rown][col]);
                asm volatile("ldmatrix.sync.aligned.m8n8.x2.shared.b16 {%0,%1}, [%2];"
                    : "=r"(b[tn][0]), "=r"(b[tn][1]) : "r"(addr));
            }
            #pragma unroll
            for (int tm = 0; tm < 2; tm++)
                #pragma unroll
                for (int tn = 0; tn < 2; tn++)
                    asm volatile("mma.sync.aligned.m16n8k16.row.col.f32.f16.f16.f32 "
                        "{%0,%1,%2,%3},{%4,%5,%6,%7},{%8,%9},{%0,%1,%2,%3};"
                        : "+f"(acc[tm][tn][0]), "+f"(acc[tm][tn][1]),
                          "+f"(acc[tm][tn][2]), "+f"(acc[tm][tn][3])
                        : "r"(a[tm][0]), "r"(a[tm][1]), "r"(a[tm][2]), "r"(a[tm][3]),
                          "r"(b[tn][0]), "r"(b[tn][1]));
        }

        // --- epilogue: fold b1 into U half, fp16 store ---
        const bool hi = (bn >= 2);
        #pragma unroll
        for (int tm = 0; tm < 2; tm++) {
            #pragma unroll
            for (int tn = 0; tn < 2; tn++) {
                int c = warp_n * 16 + tn * 8 + 2 * (lane & 3);   // within 64-col tile
                float bx = 0.f, by = 0.f;
                if (!hi) {
                    bx = b1[bn * 64 + c];
                    by = b1[bn * 64 + c + 1];
                }
                int r0 = m0 + warp_m * 32 + tm * 16 + (lane >> 2);
                int r1 = r0 + 8;
                if (r0 < N_NODES)
                    *(__half2*)(g_UVh + (size_t)r0 * 256 + bn * 64 + c) =
                        __floats2half2_rn(acc[tm][tn][0] + bx, acc[tm][tn][1] + by);
                if (r1 < N_NODES)
                    *(__half2*)(g_UVh + (size_t)r1 * 256 + bn * 64 + c) =
                        __floats2half2_rn(acc[tm][tn][2] + bx, acc[tm][tn][3] + by);
            }
        }
    }
}

// ---------------------------------------------------------------------------
// Kernel 2: edge epilogue. 8 lanes per edge, 4 edges per warp, half2 math.
//   h = relu(U'[e0] + V[e1]);  out = sigmoid(h . W2 + b2)
// Lane loads 32B from U and 32B from V (16 hidden units each).
// ---------------------------------------------------------------------------
__global__ __launch_bounds__(256) void edge_kernel(
    const int* __restrict__ e32,
    const float* __restrict__ W2, const float* __restrict__ b2,
    float* __restrict__ out)
{
    __shared__ int is64s;
    const int tid = threadIdx.x;
    if (tid == 0) {
        int any_hi = 0;
        #pragma unroll
        for (int i = 1; i < 64; i += 2) any_hi |= e32[i];
        is64s = (any_hi == 0);
    }
    __syncthreads();
    const int is64 = is64s;

    const int warp = tid >> 5, lane = tid & 31;
    const int g  = lane >> 3;        // 0..3: which edge of the quad
    const int sl = lane & 7;         // lane within edge group

    // W2 slice: 16 fp32 -> 8 half2 registers
    __half2 w2h[8];
    #pragma unroll
    for (int q = 0; q < 4; q++) {
        float4 w = *(const float4*)(W2 + sl * 16 + q * 4);
        w2h[q * 2]     = __floats2half2_rn(w.x, w.y);
        w2h[q * 2 + 1] = __floats2half2_rn(w.z, w.w);
    }
    const float bias2 = __ldg(b2);
    const long long* e64 = (const long long*)e32;

    const int gw = blockIdx.x * 8 + warp;
    const int stride = gridDim.x * 8 * 4;
    const __half2 z2 = __float2half2_rn(0.f);

    for (int e = gw * 4 + g; e < N_EDGES; e += stride) {
        int s, t;
        if (is64) {
            s = (int)e64[e];
            t = (int)e64[(size_t)N_EDGES + e];
        } else {
            s = e32[e];
            t = e32[(size_t)N_EDGES + e];
        }

        const uint4* up = (const uint4*)(g_UVh + (size_t)s * 256 + sl * 16);
        const uint4* vp = (const uint4*)(g_UVh + (size_t)t * 256 + 128 + sl * 16);
        uint4 ua = up[0], ub = up[1];
        uint4 va = vp[0], vb = vp[1];

        __half2 acc2;
        {
            __half2 h;
            h = __hmax2(__hadd2(*(__half2*)&ua.x, *(__half2*)&va.x), z2);
            acc2 = __hmul2(h, w2h[0]);
            h = __hmax2(__hadd2(*(__half2*)&ua.y, *(__half2*)&va.y), z2);
            acc2 = __hfma2(h, w2h[1], acc2);
            h = __hmax2(__hadd2(*(__half2*)&ua.z, *(__half2*)&va.z), z2);
            acc2 = __hfma2(h, w2h[2], acc2);
            h = __hmax2(__hadd2(*(__half2*)&ua.w, *(__half2*)&va.w), z2);
            acc2 = __hfma2(h, w2h[3], acc2);
            h = __hmax2(__hadd2(*(__half2*)&ub.x, *(__half2*)&vb.x), z2);
            acc2 = __hfma2(h, w2h[4], acc2);
            h = __hmax2(__hadd2(*(__half2*)&ub.y, *(__half2*)&vb.y), z2);
            acc2 = __hfma2(h, w2h[5], acc2);
            h = __hmax2(__hadd2(*(__half2*)&ub.z, *(__half2*)&vb.z), z2);
            acc2 = __hfma2(h, w2h[6], acc2);
            h = __hmax2(__hadd2(*(__half2*)&ub.w, *(__half2*)&vb.w), z2);
            acc2 = __hfma2(h, w2h[7], acc2);
        }
        float2 af = __half22float2(acc2);
        float acc = af.x + af.y;

        acc += __shfl_xor_sync(0xFFFFFFFFu, acc, 4);
        acc += __shfl_xor_sync(0xFFFFFFFFu, acc, 2);
        acc += __shfl_xor_sync(0xFFFFFFFFu, acc, 1);

        if (sl == 0) {
            float logit = acc + bias2;
            out[e] = 1.0f / (1.0f + expf(-logit));
        }
    }
}

// ---------------------------------------------------------------------------
extern "C" void kernel_launch(void* const* d_in, const int* in_sizes, int n_in,
                              void* d_out, int out_size)
{
    const float* z  = (const float*)d_in[0];
    const int*   e  = (const int*)d_in[1];
    const float* W1 = (const float*)d_in[2];
    const float* b1 = (const float*)d_in[3];
    const float* W2 = (const float*)d_in[4];
    const float* b2 = (const float*)d_in[5];
    float* out = (float*)d_out;

    w1_convert<<<128, 256>>>(W1);
    uv_gemm_tc<<<(N_NODES + 63) / 64, 256>>>(z, b1);
    edge_kernel<<<1184, 256>>>(e, W2, b2, out);
}